// round 1
// baseline (speedup 1.0000x reference)
#include <cuda_runtime.h>
#include <cstdint>

#define K_DIM 1024
#define M_DIM 2048
#define N_DIM 1024

// Scratch (static __device__ arrays: allocation-free per harness rules)
__device__ float  g_XC[K_DIM * M_DIM];   // [k][m], (x + vmap)/16, transposed
__device__ float2 g_WC[K_DIM * N_DIM];   // [k][n], (w + wmap) duplicated pairs

// ---------------------------------------------------------------------------
// Prep W: convert + duplicate into float2 pairs. grid=1024, block=256.
// ---------------------------------------------------------------------------
__global__ void prep_w_kernel(const float* __restrict__ W,
                              const float* __restrict__ wmap) {
    int k = blockIdx.x;
    int j = k & 15;
    int n = threadIdx.x * 4;
    float4 w4 = *(const float4*)(W + k * N_DIM + n);
    float2* dst = g_WC + k * N_DIM + n;
    float vals[4] = {w4.x, w4.y, w4.z, w4.w};
#pragma unroll
    for (int e = 0; e < 4; e++) {
        float w = vals[e];
        int idx = (int)(w + 8.0f);
        idx = idx < 0 ? 0 : (idx > 15 ? 15 : idx);
        float wc = w + __ldg(wmap + j * 16 + idx);
        dst[e] = make_float2(wc, wc);
    }
}

// ---------------------------------------------------------------------------
// Prep X: convert (+ fold 1/16 scale) + transpose [m][k] -> [k][m].
// grid=(32,64) block=(32,8).
// ---------------------------------------------------------------------------
__global__ void prep_x_kernel(const float* __restrict__ X,
                              const float* __restrict__ vmap) {
    __shared__ float tile[32][33];
    int k0 = blockIdx.x * 32;
    int m0 = blockIdx.y * 32;
    int tx = threadIdx.x;
    int ty = threadIdx.y;
#pragma unroll
    for (int i = 0; i < 32; i += 8) {
        int m = m0 + ty + i;
        int k = k0 + tx;
        float v = X[m * K_DIM + k];
        int j = k & 15;
        int idx = (int)(v + 8.0f);
        idx = idx < 0 ? 0 : (idx > 15 ? 15 : idx);
        tile[ty + i][tx] = (v + __ldg(vmap + j * 16 + idx)) * 0.0625f;
    }
    __syncthreads();
#pragma unroll
    for (int i = 0; i < 32; i += 8) {
        g_XC[(k0 + ty + i) * M_DIM + m0 + tx] = tile[tx][ty + i];
    }
}

// ---------------------------------------------------------------------------
// Main: 64 chunks of rank-16 GEMM, per-chunk ADC round, int accumulate.
// Block tile 128(m) x 64(n), 256 threads, 8x4 outputs/thread (m-paired f32x2).
// grid=(16,16).
// ---------------------------------------------------------------------------
__global__ void __launch_bounds__(256, 2)
opu_main_kernel(float* __restrict__ out) {
    __shared__ float  sX[16][132];   // [j][m_local], pad for STS banks
    __shared__ float2 sW[16][68];    // [j][n_local] duplicated pairs

    const int t  = threadIdx.x;
    const int m0 = blockIdx.x * 128;
    const int n0 = blockIdx.y * 64;
    const int tm = t >> 4;           // 0..15 -> rows tm*8 .. tm*8+7
    const int tn = t & 15;           // 0..15 -> cols tn*4 .. tn*4+3

    // staging assignment: 16 threads per j row
    const int jl     = t >> 4;       // 0..15
    const int mstage = (t & 15) * 8; // 8 floats of X per thread
    const int nstage = (t & 15) * 4; // 4 float2 pairs of W per thread

    unsigned su[32];
#pragma unroll
    for (int i = 0; i < 32; i++) su[i] = 0u;

    const unsigned long long C2 = 0x4B4000004B400000ULL;  // (1.5*2^23, 1.5*2^23)

    // prefetch chunk 0
    float4 px0, px1, pw0, pw1;
    {
        const float4* xp = (const float4*)(g_XC + (size_t)jl * M_DIM + m0 + mstage);
        px0 = xp[0]; px1 = xp[1];
        const float4* wp = (const float4*)(g_WC + (size_t)jl * N_DIM + n0 + nstage);
        pw0 = wp[0]; pw1 = wp[1];
    }

    for (int r = 0; r < 64; r++) {
        // stage current chunk into smem
        *(float4*)&sX[jl][mstage]     = px0;
        *(float4*)&sX[jl][mstage + 4] = px1;
        *(float4*)&sW[jl][nstage]     = pw0;
        *(float4*)&sW[jl][nstage + 2] = pw1;
        __syncthreads();

        // prefetch next chunk (LDG latency overlaps compute)
        if (r < 63) {
            const int kb = (r + 1) * 16 + jl;
            const float4* xp = (const float4*)(g_XC + (size_t)kb * M_DIM + m0 + mstage);
            px0 = xp[0]; px1 = xp[1];
            const float4* wp = (const float4*)(g_WC + (size_t)kb * N_DIM + n0 + nstage);
            pw0 = wp[0]; pw1 = wp[1];
        }

        unsigned long long acc[16];
#pragma unroll
        for (int i = 0; i < 16; i++) acc[i] = 0ULL;  // (0.0f, 0.0f)

#pragma unroll
        for (int j = 0; j < 16; j++) {
            // A: 4 row-pairs (m, m+1) ; B: 4 duplicated col scalars (w, w)
            ulonglong2 axy = *(const ulonglong2*)&sX[j][tm * 8];
            ulonglong2 azw = *(const ulonglong2*)&sX[j][tm * 8 + 4];
            ulonglong2 b01 = *(const ulonglong2*)&sW[j][tn * 4];
            ulonglong2 b23 = *(const ulonglong2*)&sW[j][tn * 4 + 2];
            unsigned long long A[4] = {axy.x, axy.y, azw.x, azw.y};
            unsigned long long B[4] = {b01.x, b01.y, b23.x, b23.y};
#pragma unroll
            for (int p = 0; p < 4; p++)
#pragma unroll
                for (int n = 0; n < 4; n++)
                    asm("fma.rn.f32x2 %0, %1, %2, %0;"
                        : "+l"(acc[p * 4 + n]) : "l"(A[p]), "l"(B[n]));
        }

        // ADC epilogue: acc holds mm/16; add magic constant -> RNE-rounded
        // integer in low mantissa bits. Clip never fires (|mm/16| <= 67).
#pragma unroll
        for (int i = 0; i < 16; i++) {
            unsigned long long tt;
            asm("add.rn.f32x2 %0, %1, %2;" : "=l"(tt) : "l"(acc[i]), "l"(C2));
            su[2 * i]     += (unsigned)tt;           // even row
            su[2 * i + 1] += (unsigned)(tt >> 32);   // odd row
        }
        __syncthreads();
    }

    // out = 16 * sum_r rint(mm_r/16); remove 64 * bias (mod 2^32): 64*0x4B400000
    const unsigned BIAS64 = 0xD0000000u;
#pragma unroll
    for (int p = 0; p < 4; p++) {
#pragma unroll
        for (int half = 0; half < 2; half++) {
            int row = m0 + tm * 8 + 2 * p + half;
            float4 o;
            o.x = 16.0f * (float)(int)(su[2 * (p * 4 + 0) + half] - BIAS64);
            o.y = 16.0f * (float)(int)(su[2 * (p * 4 + 1) + half] - BIAS64);
            o.z = 16.0f * (float)(int)(su[2 * (p * 4 + 2) + half] - BIAS64);
            o.w = 16.0f * (float)(int)(su[2 * (p * 4 + 3) + half] - BIAS64);
            *(float4*)(out + (size_t)row * N_DIM + n0 + tn * 4) = o;
        }
    }
}

// ---------------------------------------------------------------------------
extern "C" void kernel_launch(void* const* d_in, const int* in_sizes, int n_in,
                              void* d_out, int out_size) {
    const float* X    = (const float*)d_in[0];  // (2,1024,1024)
    const float* W    = (const float*)d_in[1];  // (1024,1024)
    const float* vmap = (const float*)d_in[2];  // (16,16)
    const float* wmap = (const float*)d_in[3];  // (16,16)
    float* out = (float*)d_out;                 // (2,1024,1024)

    prep_w_kernel<<<1024, 256>>>(W, wmap);
    prep_x_kernel<<<dim3(32, 64), dim3(32, 8)>>>(X, vmap);
    opu_main_kernel<<<dim3(16, 16), 256>>>(out);
}

// round 2
// speedup vs baseline: 1.6405x; 1.6405x over previous
#include <cuda_runtime.h>
#include <cstdint>

#define K_DIM 1024
#define M_DIM 2048
#define N_DIM 1024

// Scratch (static __device__ arrays: allocation-free per harness rules)
__device__ float  g_XC[K_DIM * M_DIM];   // [k][m], (x + vmap)/16, transposed
__device__ float2 g_WC[K_DIM * N_DIM];   // [k][n], (w + wmap) duplicated pairs

// ---------------------------------------------------------------------------
// Prep W: convert + duplicate into float2 pairs. grid=1024, block=256.
// ---------------------------------------------------------------------------
__global__ void prep_w_kernel(const float* __restrict__ W,
                              const float* __restrict__ wmap) {
    int k = blockIdx.x;
    int j = k & 15;
    int n = threadIdx.x * 4;
    float4 w4 = *(const float4*)(W + k * N_DIM + n);
    float vals[4] = {w4.x, w4.y, w4.z, w4.w};
    float wc[4];
#pragma unroll
    for (int e = 0; e < 4; e++) {
        float w = vals[e];
        int idx = (int)(w + 8.0f);
        idx = idx < 0 ? 0 : (idx > 15 ? 15 : idx);
        wc[e] = w + __ldg(wmap + j * 16 + idx);
    }
    float4* dst = (float4*)(g_WC + k * N_DIM + n);
    dst[0] = make_float4(wc[0], wc[0], wc[1], wc[1]);
    dst[1] = make_float4(wc[2], wc[2], wc[3], wc[3]);
}

// ---------------------------------------------------------------------------
// Prep X: convert (+ fold 1/16 scale) + transpose [m][k] -> [k][m].
// grid=(32,64) block=(32,8).
// ---------------------------------------------------------------------------
__global__ void prep_x_kernel(const float* __restrict__ X,
                              const float* __restrict__ vmap) {
    __shared__ float tile[32][33];
    int k0 = blockIdx.x * 32;
    int m0 = blockIdx.y * 32;
    int tx = threadIdx.x;
    int ty = threadIdx.y;
#pragma unroll
    for (int i = 0; i < 32; i += 8) {
        int m = m0 + ty + i;
        int k = k0 + tx;
        float v = X[m * K_DIM + k];
        int j = k & 15;
        int idx = (int)(v + 8.0f);
        idx = idx < 0 ? 0 : (idx > 15 ? 15 : idx);
        tile[ty + i][tx] = (v + __ldg(vmap + j * 16 + idx)) * 0.0625f;
    }
    __syncthreads();
#pragma unroll
    for (int i = 0; i < 32; i += 8) {
        g_XC[(k0 + ty + i) * M_DIM + m0 + tx] = tile[tx][ty + i];
    }
}

// ---------------------------------------------------------------------------
// Main: 64 chunks of rank-16 GEMM, per-chunk ADC round, int accumulate.
// Block tile 128(m) x 64(n), 256 threads, 8x4 outputs/thread (m-paired f32x2).
// Thread (tm,tn) owns rows tm*8..+7 and cols {2tn, 2tn+1, 2tn+32, 2tn+33}.
// cp.async double-buffered staging; all smem accesses conflict-free.
// grid=(16,16).
// ---------------------------------------------------------------------------
__global__ void __launch_bounds__(256, 2)
opu_main_kernel(float* __restrict__ out) {
    __shared__ float sX[2][16 * 128];    // [buf][j*128 + m_local], 512 B rows
    __shared__ float2 sW[2][16 * 64];    // [buf][j*64 + n_local] dup pairs, 512 B rows

    const int t  = threadIdx.x;
    const int m0 = blockIdx.x * 128;
    const int n0 = blockIdx.y * 64;
    const int tm = t >> 4;               // 0..15
    const int tn = t & 15;               // 0..15

    // cp.async staging: each thread copies two 16-B segments per image.
    const int jw    = t >> 5;            // 0..7 (j row for segment 1; +8 for seg 2)
    const int inner = (t & 31) * 16;     // byte offset within 512-B row

    const char* srcx = (const char*)g_XC + ((size_t)jw * M_DIM + m0) * 4 + inner;
    const char* srcw = (const char*)g_WC + ((size_t)jw * N_DIM + n0) * 8 + inner;
    const size_t xstride = (size_t)16 * M_DIM * 4;   // bytes per chunk
    const size_t wstride = (size_t)16 * N_DIM * 8;
    const size_t xhalf   = (size_t)8 * M_DIM * 4;    // j+8 row offset
    const size_t whalf   = (size_t)8 * N_DIM * 8;

    const unsigned sx_base = (unsigned)__cvta_generic_to_shared(&sX[0][0]);
    const unsigned sw_base = (unsigned)__cvta_generic_to_shared(&sW[0][0]);
    const unsigned dx = jw * 512 + inner;
    const unsigned dw = jw * 512 + inner;

#define ISSUE_CHUNK(r)                                                         \
    do {                                                                       \
        unsigned b = ((r) & 1) ? 8192u : 0u;                                   \
        const char* sx1 = srcx + (size_t)(r) * xstride;                        \
        const char* sw1 = srcw + (size_t)(r) * wstride;                        \
        asm volatile("cp.async.cg.shared.global [%0], [%1], 16;" ::            \
                     "r"(sx_base + b + dx), "l"(sx1));                         \
        asm volatile("cp.async.cg.shared.global [%0], [%1], 16;" ::            \
                     "r"(sx_base + b + dx + 4096u), "l"(sx1 + xhalf));         \
        asm volatile("cp.async.cg.shared.global [%0], [%1], 16;" ::            \
                     "r"(sw_base + b + dw), "l"(sw1));                         \
        asm volatile("cp.async.cg.shared.global [%0], [%1], 16;" ::            \
                     "r"(sw_base + b + dw + 4096u), "l"(sw1 + whalf));         \
        asm volatile("cp.async.commit_group;");                                \
    } while (0)

    unsigned su[32];
#pragma unroll
    for (int i = 0; i < 32; i++) su[i] = 0u;

    const unsigned long long C2 = 0x4B4000004B400000ULL;  // (1.5*2^23, 1.5*2^23)

    ISSUE_CHUNK(0);

    for (int r = 0; r < 64; r++) {
        asm volatile("cp.async.wait_group 0;" ::: "memory");
        __syncthreads();
        if (r < 63) ISSUE_CHUNK(r + 1);

        const char* xb = (const char*)&sX[r & 1][0];
        const char* wb = (const char*)&sW[r & 1][0];

        unsigned long long acc[16];
#pragma unroll
        for (int i = 0; i < 16; i++) acc[i] = 0ULL;

#pragma unroll
        for (int j = 0; j < 16; j++) {
            // A: 4 row-pairs (m,m+1), broadcast-friendly (2 addrs/warp)
            ulonglong2 axy = *(const ulonglong2*)(xb + j * 512 + tm * 32);
            ulonglong2 azw = *(const ulonglong2*)(xb + j * 512 + tm * 32 + 16);
            // B: dup pairs for cols {2tn,2tn+1} and {2tn+32,2tn+33};
            // stride-16 addrs across lanes -> conflict-free
            ulonglong2 b01 = *(const ulonglong2*)(wb + j * 512 + tn * 16);
            ulonglong2 b23 = *(const ulonglong2*)(wb + j * 512 + 256 + tn * 16);
            unsigned long long A[4] = {axy.x, axy.y, azw.x, azw.y};
            unsigned long long B[4] = {b01.x, b01.y, b23.x, b23.y};
#pragma unroll
            for (int p = 0; p < 4; p++)
#pragma unroll
                for (int q = 0; q < 4; q++)
                    asm("fma.rn.f32x2 %0, %1, %2, %0;"
                        : "+l"(acc[p * 4 + q]) : "l"(A[p]), "l"(B[q]));
        }

        // ADC: acc holds mm/16; +magic -> RNE integer in low mantissa bits.
        // Clip never fires (|mm/16| <= 67 < 127.5).
#pragma unroll
        for (int i = 0; i < 16; i++) {
            unsigned long long tt;
            asm("add.rn.f32x2 %0, %1, %2;" : "=l"(tt) : "l"(acc[i]), "l"(C2));
            su[2 * i]     += (unsigned)tt;           // even row of pair
            su[2 * i + 1] += (unsigned)(tt >> 32);   // odd row
        }
    }

    // out = 16 * sum_r rint(mm_r/16); remove 64*0x4B400000 mod 2^32
    const unsigned BIAS64 = 0xD0000000u;
#pragma unroll
    for (int p = 0; p < 4; p++) {
#pragma unroll
        for (int half = 0; half < 2; half++) {
            int row = m0 + tm * 8 + 2 * p + half;
            float2 o1, o2;
            o1.x = 16.0f * (float)(int)(su[2 * (p * 4 + 0) + half] - BIAS64);
            o1.y = 16.0f * (float)(int)(su[2 * (p * 4 + 1) + half] - BIAS64);
            o2.x = 16.0f * (float)(int)(su[2 * (p * 4 + 2) + half] - BIAS64);
            o2.y = 16.0f * (float)(int)(su[2 * (p * 4 + 3) + half] - BIAS64);
            float* orow = out + (size_t)row * N_DIM + n0;
            *(float2*)(orow + 2 * tn)      = o1;
            *(float2*)(orow + 32 + 2 * tn) = o2;
        }
    }
#undef ISSUE_CHUNK
}

// ---------------------------------------------------------------------------
extern "C" void kernel_launch(void* const* d_in, const int* in_sizes, int n_in,
                              void* d_out, int out_size) {
    const float* X    = (const float*)d_in[0];  // (2,1024,1024)
    const float* W    = (const float*)d_in[1];  // (1024,1024)
    const float* vmap = (const float*)d_in[2];  // (16,16)
    const float* wmap = (const float*)d_in[3];  // (16,16)
    float* out = (float*)d_out;                 // (2,1024,1024)

    prep_w_kernel<<<1024, 256>>>(W, wmap);
    prep_x_kernel<<<dim3(32, 64), dim3(32, 8)>>>(X, vmap);
    opu_main_kernel<<<dim3(16, 16), 256>>>(out);
}

// round 4
// speedup vs baseline: 2.7148x; 1.6549x over previous
#include <cuda_runtime.h>
#include <cuda_fp16.h>
#include <cstdint>

#define K_DIM 1024
#define M_DIM 2048
#define N_DIM 1024
#define NCHUNK 64

// fp16 split operand planes, K-concatenated per chunk (64 halves = 128 B per row)
__device__ __half g_A[(size_t)NCHUNK * M_DIM * 64];  // [r][m][hi16|hi16|lo16|lo16]
__device__ __half g_B[(size_t)NCHUNK * N_DIM * 64];  // [r][n][whi|wlo|whi|wlo]

// ---------------------------------------------------------------------------
// Prep X: x_c/16 -> fp16 hi/lo planes. grid=512, block=256 (one thread per (r,m))
// ---------------------------------------------------------------------------
__global__ void prep_x_kernel(const float* __restrict__ X,
                              const float* __restrict__ vmap) {
    int gid = blockIdx.x * 256 + threadIdx.x;      // 64*2048
    int r = gid >> 11, m = gid & 2047;
    const float* src = X + (size_t)m * K_DIM + r * 16;
    float xs[16];
    ((float4*)xs)[0] = ((const float4*)src)[0];
    ((float4*)xs)[1] = ((const float4*)src)[1];
    ((float4*)xs)[2] = ((const float4*)src)[2];
    ((float4*)xs)[3] = ((const float4*)src)[3];
    unsigned hi[8], lo[8];
#pragma unroll
    for (int jj = 0; jj < 8; jj++) {
        unsigned short h[2], l[2];
#pragma unroll
        for (int e = 0; e < 2; e++) {
            int j = 2 * jj + e;
            float xv = xs[j];
            int idx = (int)(xv + 8.0f);
            idx = idx < 0 ? 0 : (idx > 15 ? 15 : idx);
            float xc = (xv + __ldg(vmap + j * 16 + idx)) * 0.0625f;
            __half hh = __float2half_rn(xc);
            __half ll = __float2half_rn(xc - __half2float(hh));
            h[e] = __half_as_ushort(hh);
            l[e] = __half_as_ushort(ll);
        }
        hi[jj] = h[0] | ((unsigned)h[1] << 16);
        lo[jj] = l[0] | ((unsigned)l[1] << 16);
    }
    uint4* dst = (uint4*)(g_A + ((size_t)r * M_DIM + m) * 64);
    uint4 H0 = make_uint4(hi[0], hi[1], hi[2], hi[3]);
    uint4 H1 = make_uint4(hi[4], hi[5], hi[6], hi[7]);
    uint4 L0 = make_uint4(lo[0], lo[1], lo[2], lo[3]);
    uint4 L1 = make_uint4(lo[4], lo[5], lo[6], lo[7]);
    dst[0] = H0; dst[1] = H1; dst[2] = H0; dst[3] = H1;  // hi | hi
    dst[4] = L0; dst[5] = L1; dst[6] = L0; dst[7] = L1;  // lo | lo
}

// ---------------------------------------------------------------------------
// Prep W: w_c -> fp16 hi/lo planes. grid=(64,4), block=256
// ---------------------------------------------------------------------------
__global__ void prep_w_kernel(const float* __restrict__ W,
                              const float* __restrict__ wmap) {
    int r = blockIdx.x;
    int n = blockIdx.y * 256 + threadIdx.x;
    unsigned hi[8], lo[8];
#pragma unroll
    for (int jj = 0; jj < 8; jj++) {
        unsigned short h[2], l[2];
#pragma unroll
        for (int e = 0; e < 2; e++) {
            int j = 2 * jj + e;
            float w = W[(size_t)(16 * r + j) * N_DIM + n];
            int idx = (int)(w + 8.0f);
            idx = idx < 0 ? 0 : (idx > 15 ? 15 : idx);
            float wc = w + __ldg(wmap + j * 16 + idx);
            __half hh = __float2half_rn(wc);
            __half ll = __float2half_rn(wc - __half2float(hh));
            h[e] = __half_as_ushort(hh);
            l[e] = __half_as_ushort(ll);
        }
        hi[jj] = h[0] | ((unsigned)h[1] << 16);
        lo[jj] = l[0] | ((unsigned)l[1] << 16);
    }
    uint4* dst = (uint4*)(g_B + ((size_t)r * N_DIM + n) * 64);
    uint4 H0 = make_uint4(hi[0], hi[1], hi[2], hi[3]);
    uint4 H1 = make_uint4(hi[4], hi[5], hi[6], hi[7]);
    uint4 L0 = make_uint4(lo[0], lo[1], lo[2], lo[3]);
    uint4 L1 = make_uint4(lo[4], lo[5], lo[6], lo[7]);
    dst[0] = H0; dst[1] = H1; dst[2] = L0; dst[3] = L1;  // whi | wlo
    dst[4] = H0; dst[5] = H1; dst[6] = L0; dst[7] = L1;  // whi | wlo
}

// ---------------------------------------------------------------------------
#define LDSM4(R, addr)                                                         \
    asm volatile("ldmatrix.sync.aligned.m8n8.x4.shared.b16 {%0,%1,%2,%3}, [%4];" \
                 : "=r"((R)[0]), "=r"((R)[1]), "=r"((R)[2]), "=r"((R)[3])      \
                 : "r"(addr))

#define MMA16816(C, A0, A1, A2, A3, B0, B1)                                    \
    asm volatile("mma.sync.aligned.m16n8k16.row.col.f32.f16.f16.f32 "          \
                 "{%0,%1,%2,%3}, {%4,%5,%6,%7}, {%8,%9}, {%0,%1,%2,%3};"       \
                 : "+f"((C)[0]), "+f"((C)[1]), "+f"((C)[2]), "+f"((C)[3])      \
                 : "r"(A0), "r"(A1), "r"(A2), "r"(A3), "r"(B0), "r"(B1))

// ---------------------------------------------------------------------------
// Main: per chunk: cp.async tiles -> HMMA (fp16 split, K=64) -> RNE -> int acc
// CTA tile 128m x 64n, 8 warps as 4(m) x 2(n), warp tile 32m x 32n.
// grid (16,16), 2 CTA/SM, double-buffered smem.
// ---------------------------------------------------------------------------
__global__ void __launch_bounds__(256, 2)
opu_main_kernel(float* __restrict__ out) {
    __shared__ __align__(1024) char sA[2][16384];   // 128 rows x 128 B, swizzled
    __shared__ __align__(1024) char sB[2][8192];    // 64 rows x 128 B, swizzled

    const int t = threadIdx.x, wid = t >> 5, lane = t & 31;
    const int m0 = blockIdx.x * 128, n0 = blockIdx.y * 64;
    const int wm = (wid >> 1) * 32, wn = (wid & 1) * 32;

    const unsigned sa = (unsigned)__cvta_generic_to_shared(&sA[0][0]);
    const unsigned sb = (unsigned)__cvta_generic_to_shared(&sB[0][0]);

    // ---- cp.async staging geometry: 16-B granules, xor swizzle (g ^ (row&7))
    int arow[4], agc[4], brow[2], bgc[2];
    unsigned adst[4], bdst[2];
#pragma unroll
    for (int i = 0; i < 4; i++) {
        int gid = t + 256 * i;
        arow[i] = gid >> 3; agc[i] = gid & 7;
        adst[i] = arow[i] * 128 + ((agc[i] ^ (arow[i] & 7)) << 4);
    }
#pragma unroll
    for (int i = 0; i < 2; i++) {
        int gid = t + 256 * i;
        brow[i] = gid >> 3; bgc[i] = gid & 7;
        bdst[i] = brow[i] * 128 + ((bgc[i] ^ (brow[i] & 7)) << 4);
    }

#define STAGE_CHUNK(r, buf)                                                     \
    do {                                                                        \
        _Pragma("unroll")                                                       \
        for (int i = 0; i < 4; i++) {                                           \
            const void* s = g_A + ((size_t)(r) * M_DIM + m0 + arow[i]) * 64 +   \
                            agc[i] * 8;                                         \
            asm volatile("cp.async.cg.shared.global [%0], [%1], 16;" ::         \
                         "r"(sa + (buf) * 16384u + adst[i]), "l"(s));           \
        }                                                                       \
        _Pragma("unroll")                                                       \
        for (int i = 0; i < 2; i++) {                                           \
            const void* s = g_B + ((size_t)(r) * N_DIM + n0 + brow[i]) * 64 +   \
                            bgc[i] * 8;                                         \
            asm volatile("cp.async.cg.shared.global [%0], [%1], 16;" ::         \
                         "r"(sb + (buf) * 8192u + bdst[i]), "l"(s));            \
        }                                                                       \
    } while (0)

    // ---- ldmatrix per-lane address precomputation
    const int l15 = lane & 15, lhi = lane >> 4;   // A: 16 rows, k half select
    const int l7 = lane & 7, lq = lane >> 3;      // B: 8 rows, k quarter select
    unsigned abase[2]; int asw[2];
#pragma unroll
    for (int i = 0; i < 2; i++) {
        int rrow = wm + 16 * i + l15;
        abase[i] = rrow * 128; asw[i] = rrow & 7;
    }
    unsigned bbase[4]; int bsw[4];
#pragma unroll
    for (int j = 0; j < 4; j++) {
        int rn = wn + 8 * j + l7;
        bbase[j] = rn * 128; bsw[j] = rn & 7;
    }

    unsigned su[2][4][4];
#pragma unroll
    for (int i = 0; i < 2; i++)
#pragma unroll
        for (int j = 0; j < 4; j++)
#pragma unroll
            for (int e = 0; e < 4; e++) su[i][j][e] = 0u;

    STAGE_CHUNK(0, 0);
    asm volatile("cp.async.commit_group;");
    STAGE_CHUNK(1, 1);
    asm volatile("cp.async.commit_group;");

    for (int r = 0; r < NCHUNK; r++) {
        const int b = r & 1;
        asm volatile("cp.async.wait_group 1;" ::: "memory");
        __syncthreads();

        float acc[2][4][4];
#pragma unroll
        for (int i = 0; i < 2; i++)
#pragma unroll
            for (int j = 0; j < 4; j++)
#pragma unroll
                for (int e = 0; e < 4; e++) acc[i][j][e] = 0.0f;

#pragma unroll
        for (int p = 0; p < 2; p++) {
            unsigned bfr[4][4];
#pragma unroll
            for (int j = 0; j < 4; j++)
                LDSM4(bfr[j], sb + b * 8192u + bbase[j] +
                               ((unsigned)(((4 * p + lq) ^ bsw[j])) << 4));
            unsigned afr[2][2][4];
#pragma unroll
            for (int i = 0; i < 2; i++)
#pragma unroll
                for (int kk = 0; kk < 2; kk++)
                    LDSM4(afr[i][kk], sa + b * 16384u + abase[i] +
                          ((unsigned)(((2 * (2 * p + kk) + lhi) ^ asw[i])) << 4));
#pragma unroll
            for (int i = 0; i < 2; i++)
#pragma unroll
                for (int j = 0; j < 4; j++) {
                    MMA16816(acc[i][j], afr[i][0][0], afr[i][0][1], afr[i][0][2],
                             afr[i][0][3], bfr[j][0], bfr[j][1]);
                    MMA16816(acc[i][j], afr[i][1][0], afr[i][1][1], afr[i][1][2],
                             afr[i][1][3], bfr[j][2], bfr[j][3]);
                }
        }

        // ADC: acc = mm/16; +magic (1.5*2^23) -> RNE int in mantissa; int acc.
        // Clip never fires (|mm/16| <= 67 < 127.5).
#pragma unroll
        for (int i = 0; i < 2; i++)
#pragma unroll
            for (int j = 0; j < 4; j++)
#pragma unroll
                for (int e = 0; e < 4; e++) {
                    float tt = acc[i][j][e] + 12582912.0f;
                    su[i][j][e] += __float_as_uint(tt);
                }

        __syncthreads();
        if (r + 2 < NCHUNK) STAGE_CHUNK(r + 2, b);
        asm volatile("cp.async.commit_group;");
    }

    // out = 16 * (su - 64*0x4B400000 mod 2^32)
    const unsigned BIAS64 = 0xD0000000u;
    const int g = lane >> 2, tg = lane & 3;
#pragma unroll
    for (int i = 0; i < 2; i++)
#pragma unroll
        for (int h = 0; h < 2; h++) {
            int row = m0 + wm + 16 * i + 8 * h + g;
            float* orow = out + (size_t)row * N_DIM + n0 + wn + 2 * tg;
#pragma unroll
            for (int j = 0; j < 4; j++) {
                float2 o;
                o.x = 16.0f * (float)(int)(su[i][j][2 * h + 0] - BIAS64);
                o.y = 16.0f * (float)(int)(su[i][j][2 * h + 1] - BIAS64);
                *(float2*)(orow + 8 * j) = o;
            }
        }
#undef STAGE_CHUNK
}

// ---------------------------------------------------------------------------
extern "C" void kernel_launch(void* const* d_in, const int* in_sizes, int n_in,
                              void* d_out, int out_size) {
    const float* X    = (const float*)d_in[0];  // (2,1024,1024)
    const float* W    = (const float*)d_in[1];  // (1024,1024)
    const float* vmap = (const float*)d_in[2];  // (16,16)
    const float* wmap = (const float*)d_in[3];  // (16,16)
    float* out = (float*)d_out;                 // (2,1024,1024)

    prep_x_kernel<<<512, 256>>>(X, vmap);
    prep_w_kernel<<<dim3(64, 4), 256>>>(W, wmap);
    opu_main_kernel<<<dim3(16, 16), 256>>>(out);
}